// round 7
// baseline (speedup 1.0000x reference)
#include <cuda_runtime.h>

#define BATCH 4096
#define NN 64
#define HH 16
#define FALLBACK_SIZE 12
#define NBLK2 BATCH          /* grid_kernel blocks  */
#define NBLK1 (BATCH / 2)    /* prep_kernel blocks  */

__device__ float    g_targets[BATCH * 128];   // [b][k][64]
__device__ int      g_size[BATCH];
__device__ float    g_partials[NBLK2 + NBLK1];
__device__ unsigned g_count = 0;

__device__ __forceinline__ float sigmoid3(float g) {
    float th;
    asm("tanh.approx.f32 %0, %1;" : "=f"(th) : "f"(1.5f * g));
    return fmaf(0.5f, th, 0.5f);
}

// ============ Kernel 1: hints -> targets, size, neural(hints) ============
__global__ __launch_bounds__(256) void prep_kernel(
    const float* __restrict__ hints,  // [B,2,64,16]
    const float* __restrict__ wh)     // [2,64,16]
{
    __shared__ int   s_li[8];
    __shared__ float s_warp[8];

    const int t = threadIdx.x;
    const int lane = t & 31;
    const int wid  = t >> 5;
    const int pair = blockIdx.x;

    // t bits: which(1) | k(1) | rhigh(1) | lane(5)
    const int which = t >> 7;
    const int k     = (t >> 6) & 1;
    const int rhigh = (t >> 5) & 1;
    const int r     = rhigh * 32 + lane;
    const int b     = pair * 2 + which;

    const float4* hp = (const float4*)(hints + (size_t)b * 2048 + k * 1024 + r * HH);
    const float4* wp = (const float4*)(wh + k * 1024 + r * HH);

    float tsum = 0.f, neural = 0.f;
    #pragma unroll
    for (int q = 0; q < 4; q++) {
        float4 h = hp[q];
        float4 w = wp[q];
        tsum   += h.x + h.y + h.z + h.w;
        neural += h.x * w.x + h.y * w.y + h.z * w.z + h.w * w.w;
    }
    g_targets[(size_t)b * 128 + k * 64 + r] = tsum;

    // per-warp last nonzero row index (global within the 64)
    const unsigned bal = __ballot_sync(0xffffffffu, tsum > 0.f);
    if (lane == 0) s_li[wid] = bal ? (rhigh * 32 + (31 - __clz(bal))) : -1;
    __syncthreads();

    if (t < 2) {
        const int last_r = max(s_li[t * 4 + 0], s_li[t * 4 + 1]);
        const int last_c = max(s_li[t * 4 + 2], s_li[t * 4 + 3]);
        g_size[pair * 2 + t] = (last_r >= 0 && last_c >= 0)
                               ? (max(last_r, last_c) + 1) : FALLBACK_SIZE;
    }

    // block-reduce neural -> partial
    float v = neural;
    #pragma unroll
    for (int off = 16; off > 0; off >>= 1)
        v += __shfl_xor_sync(0xffffffffu, v, off);
    if (lane == 0) s_warp[wid] = v;
    __syncthreads();
    if (t == 0) {
        float p = 0.f;
        #pragma unroll
        for (int w = 0; w < 8; w++) p += s_warp[w];
        g_partials[NBLK2 + pair] = p;
    }
}

// ============ Kernel 2: grid pass (loads fly immediately) ============
__global__ __launch_bounds__(256, 5) void grid_kernel(
    const float* __restrict__ grid,   // [B,1,64,64]
    const float* __restrict__ wg,     // [1,64,64]
    float* __restrict__ out)
{
    __shared__ float s_colpart[8 * NN];
    __shared__ float s_warp[8];
    __shared__ bool  s_is_last;
    __shared__ double s_dwarp[8];

    const int b = blockIdx.x;
    const int t = threadIdx.x;
    const int lane = t & 31;
    const int wid  = t >> 5;

    const int i  = t >> 2;            // row
    const int cg = t & 3;             // 16-col group

    const float4* gp  = (const float4*)(grid + (size_t)b * (NN * NN) + i * NN + cg * 16);
    const float4* wgp = (const float4*)(wg + i * NN + cg * 16);

    // independent small loads (L2 hits) — no barrier anywhere before these
    const int   size = g_size[b];
    const float rt   = g_targets[(size_t)b * 128 + i];          // row target
    const float ct   = (t < NN) ? g_targets[(size_t)b * 128 + 64 + t] : 0.f;
    const float sz   = (float)size;

    const bool  rin   = (i < size);
    const float rmask = rin ? 1.f : 0.f;

    float csg[16];
    float neural = 0.f, rowacc = 0.f, binsum = 0.f;

    #pragma unroll
    for (int q = 0; q < 4; q++) {
        float4 g4 = gp[q];
        float4 w4 = wgp[q];
        float gs[4] = {g4.x, g4.y, g4.z, g4.w};
        float ws[4] = {w4.x, w4.y, w4.z, w4.w};
        #pragma unroll
        for (int e = 0; e < 4; e++) {
            const int j = cg * 16 + q * 4 + e;
            const float g = gs[e];
            neural += g * ws[e];
            const float s = sigmoid3(g);
            const float jmask = (j < size) ? 1.f : 0.f;
            rowacc += s * jmask;
            binsum += g * g * jmask;
            csg[q * 4 + e] = s * rmask;
        }
    }
    binsum *= rmask;

    // actual_rows[i]: reduce across the 4 column-group lanes
    rowacc += __shfl_xor_sync(0xffffffffu, rowacc, 1);
    rowacc += __shfl_xor_sync(0xffffffffu, rowacc, 2);
    float rowerr = 0.f;
    if (cg == 0 && rin) {
        const float d = rowacc - rt;
        rowerr = d * d;
    }

    // actual_cols: reduce csg over the 8 rows in this warp (lane = ((i&7)<<2)|cg)
    #pragma unroll
    for (int x = 0; x < 16; x++) {
        csg[x] += __shfl_xor_sync(0xffffffffu, csg[x], 4);
        csg[x] += __shfl_xor_sync(0xffffffffu, csg[x], 8);
        csg[x] += __shfl_xor_sync(0xffffffffu, csg[x], 16);
    }
    if (lane < 4) {
        #pragma unroll
        for (int x = 0; x < 16; x++)
            s_colpart[wid * NN + lane * 16 + x] = csg[x];
    }
    __syncthreads();

    float colerr = 0.f;
    if (t < NN && t < size) {
        float csum = 0.f;
        #pragma unroll
        for (int w = 0; w < 8; w++) csum += s_colpart[w * NN + t];
        const float d = csum - ct;
        colerr = d * d;
    }

    float v = neural
            + (10.f / sz) * (rowerr + colerr)
            + (0.1f / (sz * sz)) * binsum;

    #pragma unroll
    for (int off = 16; off > 0; off >>= 1)
        v += __shfl_xor_sync(0xffffffffu, v, off);
    if (lane == 0) s_warp[wid] = v;
    __syncthreads();
    if (t == 0) {
        float p = 0.f;
        #pragma unroll
        for (int w = 0; w < 8; w++) p += s_warp[w];
        g_partials[b] = p;
        __threadfence();
        unsigned old = atomicInc(&g_count, NBLK2 - 1);   // wraps -> replay-safe
        s_is_last = (old == NBLK2 - 1);
    }
    __syncthreads();

    // last block: fold all partials (bit-exact deterministic)
    if (s_is_last) {
        double acc = 0.0;
        #pragma unroll
        for (int q = 0; q < (NBLK2 + NBLK1) / 256; q++)
            acc += (double)g_partials[t + q * 256];
        #pragma unroll
        for (int off = 16; off > 0; off >>= 1)
            acc += __shfl_xor_sync(0xffffffffu, acc, off);
        if (lane == 0) s_dwarp[wid] = acc;
        __syncthreads();
        if (t < 8) {
            acc = s_dwarp[t];
            acc += __shfl_xor_sync(0xffu, acc, 4);
            acc += __shfl_xor_sync(0xffu, acc, 2);
            acc += __shfl_xor_sync(0xffu, acc, 1);
            if (t == 0) out[0] = (float)(acc * (1.0 / (double)BATCH));
        }
    }
}

extern "C" void kernel_launch(void* const* d_in, const int* in_sizes, int n_in,
                              void* d_out, int out_size) {
    const float* grid  = (const float*)d_in[0];
    const float* hints = (const float*)d_in[1];
    const float* wg    = (const float*)d_in[2];
    const float* wh    = (const float*)d_in[3];
    float* out = (float*)d_out;

    prep_kernel<<<NBLK1, 256>>>(hints, wh);
    grid_kernel<<<NBLK2, 256>>>(grid, wg, out);
}

// round 10
// speedup vs baseline: 1.4578x; 1.4578x over previous
#include <cuda_runtime.h>

#define BATCH 4096
#define NN 64
#define HH 16
#define FALLBACK_SIZE 12

__device__ float    g_partials[BATCH];
__device__ unsigned g_count = 0;

__device__ __forceinline__ float sigmoid3(float g) {
    float th;
    asm("tanh.approx.f32 %0, %1;" : "=f"(th) : "f"(1.5f * g));
    return fmaf(0.5f, th, 0.5f);
}

__global__ __launch_bounds__(256, 5) void energy_kernel(
    const float* __restrict__ grid,   // [B,1,64,64]
    const float* __restrict__ hints,  // [B,2,64,16]
    const float* __restrict__ wg,     // [1,64,64]
    const float* __restrict__ wh,     // [2,64,16]
    float* __restrict__ out)
{
    __shared__ float s_row_target[NN];
    __shared__ float s_col_target[NN];
    __shared__ float s_colpart[8 * NN];
    __shared__ float s_warp[8];
    __shared__ int   s_last[2];
    __shared__ bool  s_is_last;
    __shared__ double s_dwarp[8];

    const int b = blockIdx.x;
    const int t = threadIdx.x;
    const int lane = t & 31;
    const int wid  = t >> 5;

    const float* gb = grid  + (size_t)b * (NN * NN);
    const float* hb = hints + (size_t)b * (2 * NN * HH);

    float neural = 0.f;

    // ---- Phase 1: hints -> targets (+ neural part), all 256 threads ----
    {
        const int k    = t >> 7;
        const int r    = (t >> 1) & 63;
        const int half = t & 1;
        const float4* hp = (const float4*)(hb + k * (NN * HH) + r * HH + half * 8);
        const float4* wp = (const float4*)(wh + k * (NN * HH) + r * HH + half * 8);
        float tsum = 0.f;
        #pragma unroll
        for (int q = 0; q < 2; q++) {
            float4 h = hp[q];
            float4 w = wp[q];
            tsum   += h.x + h.y + h.z + h.w;
            neural += h.x * w.x + h.y * w.y + h.z * w.z + h.w * w.w;
        }
        tsum += __shfl_xor_sync(0xffffffffu, tsum, 1);
        if (half == 0) {
            if (k == 0) s_row_target[r] = tsum;
            else        s_col_target[r] = tsum;
        }
    }
    __syncthreads();

    // ---- Phase 2: puzzle size (warps 0,1: parallel arg-scan) ----
    if (wid < 2) {
        const float* tgt = (wid == 0) ? s_row_target : s_col_target;
        int v0 = (tgt[lane]      > 0.f) ? lane      : -1;
        int v1 = (tgt[lane + 32] > 0.f) ? lane + 32 : -1;
        int v = max(v0, v1);
        #pragma unroll
        for (int off = 16; off > 0; off >>= 1)
            v = max(v, __shfl_xor_sync(0xffffffffu, v, off));
        if (lane == 0) s_last[wid] = v;
    }
    __syncthreads();
    const int last_r = s_last[0], last_c = s_last[1];
    const int size = (last_r >= 0 && last_c >= 0) ? (max(last_r, last_c) + 1)
                                                  : FALLBACK_SIZE;
    const float sz = (float)size;

    // ---- Phase 3: grid pass, 4x4 tile per thread ----
    // warp covers 8 consecutive rows: rb = wid*2 + (lane>>4) (4-row block),
    // cb = lane&15 -> cols cb*4 .. cb*4+3
    const int rb = wid * 2 + (lane >> 4);
    const int cb = lane & 15;
    const int c0 = cb * 4;
    const int r0 = rb * 4;

    const float jm0 = (c0 + 0 < size) ? 1.f : 0.f;
    const float jm1 = (c0 + 1 < size) ? 1.f : 0.f;
    const float jm2 = (c0 + 2 < size) ? 1.f : 0.f;
    const float jm3 = (c0 + 3 < size) ? 1.f : 0.f;

    float cs0 = 0.f, cs1 = 0.f, cs2 = 0.f, cs3 = 0.f;   // col partials (4 rows)
    float rsum[4];
    float binsum = 0.f;

    #pragma unroll
    for (int rr = 0; rr < 4; rr++) {
        const int r = r0 + rr;
        float4 g = *(const float4*)(gb + r * NN + c0);
        float4 w = *(const float4*)(wg + r * NN + c0);
        neural += g.x * w.x + g.y * w.y + g.z * w.z + g.w * w.w;
        const float s0 = sigmoid3(g.x);
        const float s1 = sigmoid3(g.y);
        const float s2 = sigmoid3(g.z);
        const float s3 = sigmoid3(g.w);
        const float rm = (r < size) ? 1.f : 0.f;
        rsum[rr] = s0 * jm0 + s1 * jm1 + s2 * jm2 + s3 * jm3;
        cs0 += s0 * rm;  cs1 += s1 * rm;  cs2 += s2 * rm;  cs3 += s3 * rm;
        binsum += (g.x * g.x * jm0 + g.y * g.y * jm1 +
                   g.z * g.z * jm2 + g.w * g.w * jm3) * rm;
    }

    // Row sums: reduce each rsum[rr] across the 16 lanes sharing the row block
    #pragma unroll
    for (int rr = 0; rr < 4; rr++) {
        rsum[rr] += __shfl_xor_sync(0xffffffffu, rsum[rr], 1);
        rsum[rr] += __shfl_xor_sync(0xffffffffu, rsum[rr], 2);
        rsum[rr] += __shfl_xor_sync(0xffffffffu, rsum[rr], 4);
        rsum[rr] += __shfl_xor_sync(0xffffffffu, rsum[rr], 8);
    }
    float rowerr = 0.f;
    if (cb == 0) {
        #pragma unroll
        for (int rr = 0; rr < 4; rr++) {
            const int r = r0 + rr;
            if (r < size) {
                const float d = rsum[rr] - s_row_target[r];
                rowerr += d * d;
            }
        }
    }

    // Col partials: combine the warp's two row blocks (xor 16), then to smem
    cs0 += __shfl_xor_sync(0xffffffffu, cs0, 16);
    cs1 += __shfl_xor_sync(0xffffffffu, cs1, 16);
    cs2 += __shfl_xor_sync(0xffffffffu, cs2, 16);
    cs3 += __shfl_xor_sync(0xffffffffu, cs3, 16);
    if (lane < 16)
        *(float4*)&s_colpart[wid * NN + lane * 4] = make_float4(cs0, cs1, cs2, cs3);
    __syncthreads();

    float colerr = 0.f;
    if (t < NN && t < size) {
        float csum = 0.f;
        #pragma unroll
        for (int w = 0; w < 8; w++) csum += s_colpart[w * NN + t];
        const float d = csum - s_col_target[t];
        colerr = d * d;
    }

    // ---- Combine + block reduce ----
    float v = neural
            + (10.f / sz) * (rowerr + colerr)
            + (0.1f / (sz * sz)) * binsum;

    #pragma unroll
    for (int off = 16; off > 0; off >>= 1)
        v += __shfl_xor_sync(0xffffffffu, v, off);
    if (lane == 0) s_warp[wid] = v;
    __syncthreads();
    if (t == 0) {
        float p = 0.f;
        #pragma unroll
        for (int w = 0; w < 8; w++) p += s_warp[w];
        g_partials[b] = p;
        __threadfence();
        unsigned old = atomicInc(&g_count, BATCH - 1);   // wraps -> replay-safe
        s_is_last = (old == BATCH - 1);
    }
    __syncthreads();

    // ---- Last block: final deterministic reduction ----
    if (s_is_last) {
        double acc = 0.0;
        #pragma unroll
        for (int q = 0; q < BATCH / 256; q++)
            acc += (double)g_partials[t + q * 256];
        #pragma unroll
        for (int off = 16; off > 0; off >>= 1)
            acc += __shfl_xor_sync(0xffffffffu, acc, off);
        if (lane == 0) s_dwarp[wid] = acc;
        __syncthreads();
        if (t < 8) {
            acc = s_dwarp[t];
            acc += __shfl_xor_sync(0xffu, acc, 4);
            acc += __shfl_xor_sync(0xffu, acc, 2);
            acc += __shfl_xor_sync(0xffu, acc, 1);
            if (t == 0) out[0] = (float)(acc * (1.0 / (double)BATCH));
        }
    }
}

extern "C" void kernel_launch(void* const* d_in, const int* in_sizes, int n_in,
                              void* d_out, int out_size) {
    const float* grid  = (const float*)d_in[0];
    const float* hints = (const float*)d_in[1];
    const float* wg    = (const float*)d_in[2];
    const float* wh    = (const float*)d_in[3];
    float* out = (float*)d_out;

    energy_kernel<<<BATCH, 256>>>(grid, hints, wg, wh, out);
}